// round 13
// baseline (speedup 1.0000x reference)
#include <cuda_runtime.h>
#include <cuda_fp16.h>
#include <cstdint>

#define N_NODES 100000
#define N_GRAPHS 64
#define MAX_E    1600000
#define SCAN_B   256
#define N_SCANB  ((N_NODES + SCAN_B) / SCAN_B)   // 391 (covers i == N_NODES)

typedef unsigned long long u64;

// ---------------- f32x2 packed math (Blackwell) ------------------------------
__device__ __forceinline__ u64 pack2(float lo, float hi) {
    u64 r;
    asm("mov.b64 %0, {%1, %2};" : "=l"(r) : "f"(lo), "f"(hi));
    return r;
}
__device__ __forceinline__ void unpack2(u64 v, float& lo, float& hi) {
    asm("mov.b64 {%0, %1}, %2;" : "=f"(lo), "=f"(hi) : "l"(v));
}
__device__ __forceinline__ u64 fma2(u64 a, u64 b, u64 c) {
    u64 d;
    asm("fma.rn.f32x2 %0, %1, %2, %3;" : "=l"(d) : "l"(a), "l"(b), "l"(c));
    return d;
}

// ---------------- scratch (device globals; zero-initialized) ----------------
// Self-cleaning protocol: buffers needing zero/initial state at call start are
// reset by the END of the previous call (indeg by layer1; sums/cnt/scan state/
// counters by the fused final block). First call relies on static zero-init.
__device__ int   g_flag64;               // 1 if index buffers are int64
__device__ int   g_batch[N_NODES];
__device__ int   g_indeg[N_NODES];
__device__ float g_dinv[N_NODES];
__device__ int   g_row_ptr[N_NODES + 1];
__device__ int   g_cur[N_NODES];
__device__ u64   g_scan_flag[N_SCANB];   // hi32: status(1=agg,2=pref), lo32: value
__device__ int   g_scan_done;            // scan-block completion counter
__device__ int   g_ready;                // scan fully complete flag
__device__ int   g_done;                 // completion counter for fused final
__device__ __align__(16) int g_csr_i[MAX_E];            // src indices only
__device__ __align__(16) float4 g_pos4[N_NODES];        // dinv-scaled pos
__device__ __align__(16) __half g_h16[N_NODES * 64];    // scaled h1 activations
__device__ __align__(16) __half g_y16[N_NODES * 32];    // scaled pre-agg (stride 32)
__device__ float g_sums[N_GRAPHS * 24];
__device__ float g_cnt[N_GRAPHS];

// ---------------- prep: local dtype detect + batch + counts + degree ---------
// int64 indices (< 2^31) => every odd 32-bit word is zero. 256 samples/block,
// deterministic across blocks. Block 0 publishes g_flag64 for later kernels.
__global__ void prep_kernel(const int* __restrict__ ei, const int* __restrict__ batch, int E) {
    __shared__ int s_nz[256];
    __shared__ float scnt[N_GRAPHS];
    int t = threadIdx.x;
    s_nz[t] = ei[2 * t + 1];   // E >= 256 always (1.6M)
    __syncthreads();
    for (int off = 128; off > 0; off >>= 1) {
        if (t < off) s_nz[t] |= s_nz[t + off];
        __syncthreads();
    }
    int flag = (s_nz[0] == 0) ? 1 : 0;
    if (blockIdx.x == 0 && t == 0) g_flag64 = flag;
    int i = blockIdx.x * blockDim.x + t;
    bool node_block = (blockIdx.x * blockDim.x) < N_NODES;
    if (node_block) {
        if (t < N_GRAPHS) scnt[t] = 0.0f;
        __syncthreads();
    }
    if (i < N_NODES) {
        int g = flag ? batch[2 * i] : batch[i];
        g_batch[i] = g;
        atomicAdd(&scnt[g], 1.0f);
    }
    if (i < E) {
        int d = flag ? ei[2 * ((long long)E + i)] : ei[E + i];
        atomicAdd(&g_indeg[d], 1);
    }
    if (node_block) {
        __syncthreads();
        if (t < N_GRAPHS && scnt[t] != 0.0f) atomicAdd(&g_cnt[t], scnt[t]);
    }
}

// ---------------- fused scan + CSR fill ---------------------------------------
// Blocks 0..N_SCANB-1 run the decoupled-lookback scan over node degrees
// (391 blocks, all wave-1 resident: launch_bounds(256,4) => >=592 co-resident),
// publish g_ready; ALL blocks then fill their edge chunk.
__global__ void __launch_bounds__(256, 4)
scan_fill_kernel(const float* __restrict__ pos, const int* __restrict__ ei, int E) {
    __shared__ int warp_x[8];
    __shared__ int s_prefix;
    __shared__ int s_go;
    int t = threadIdx.x, b = blockIdx.x;
    int lane = t & 31, wid = t >> 5;
    int flag = g_flag64;

    if (b < N_SCANB) {
        int i = b * SCAN_B + t;
        int val = (i < N_NODES) ? g_indeg[i] : 0;
        if (i < N_NODES) {
            float di = rsqrtf((float)(val + 1));   // +1 self-loop
            g_dinv[i] = di;
            g_pos4[i] = make_float4(di * pos[3 * i], di * pos[3 * i + 1],
                                    di * pos[3 * i + 2], 0.0f);
        }
        // warp inclusive scan
        int x = val;
#pragma unroll
        for (int off = 1; off < 32; off <<= 1) {
            int y = __shfl_up_sync(0xFFFFFFFFu, x, off);
            if (lane >= off) x += y;
        }
        if (lane == 31) warp_x[wid] = x;
        __syncthreads();
        if (wid == 0) {
            int w = (lane < 8) ? warp_x[lane] : 0;
            int xs = w;
#pragma unroll
            for (int off = 1; off < 8; off <<= 1) {
                int y = __shfl_up_sync(0xFFFFFFFFu, xs, off);
                if (lane >= off) xs += y;
            }
            if (lane < 8) warp_x[lane] = xs - w;
            if (lane == 7) {
                u64 st = (b == 0) ? 2ULL : 1ULL;
                atomicExch(&g_scan_flag[b], (st << 32) | (unsigned int)xs);
            }
        }
        __syncthreads();
        int block_incl = x + warp_x[wid];
        // windowed lookback by warp 0
        if (wid == 0) {
            int prefix = 0;
            if (b > 0) {
                int j = b - 1;
                while (true) {
                    int idx = j - lane;
                    u64 pkt = (idx >= 0) ? atomicAdd(&g_scan_flag[idx], 0ULL) : (2ULL << 32);
                    int st = (int)(pkt >> 32);
                    unsigned rdy = __ballot_sync(0xFFFFFFFFu, st != 0);
                    if (rdy != 0xFFFFFFFFu) continue;
                    unsigned pm = __ballot_sync(0xFFFFFFFFu, st == 2);
                    int stop = pm ? (__ffs(pm) - 1) : 32;
                    int val2 = (lane <= stop) ? (int)(unsigned int)pkt : 0;
#pragma unroll
                    for (int off = 16; off > 0; off >>= 1)
                        val2 += __shfl_down_sync(0xFFFFFFFFu, val2, off);
                    prefix += __shfl_sync(0xFFFFFFFFu, val2, 0);
                    if (stop < 32) break;
                    j -= 32;
                }
            }
            if (lane == 0) s_prefix = prefix;
        }
        __syncthreads();
        int prefix = s_prefix;
        if (t == SCAN_B - 1)
            atomicExch(&g_scan_flag[b], (2ULL << 32) | (unsigned int)(prefix + block_incl));
        int excl = prefix + block_incl - val;
        if (i < N_NODES) {
            g_row_ptr[i] = excl;
            g_cur[i] = excl;
        }
        if (i == N_NODES) g_row_ptr[N_NODES] = E;
        __syncthreads();
        if (t == 0) {
            __threadfence();
            if (atomicAdd(&g_scan_done, 1) == N_SCANB - 1)
                atomicExch(&g_ready, 1);
        }
    }
    // ---- all blocks: wait for scan completion, then fill edges ----
    if (t == 0) {
        while (atomicAdd(&g_ready, 0) == 0) __nanosleep(64);
        s_go = 1;
    }
    __syncthreads();
    (void)s_go;
    __threadfence();
    int e = b * 256 + t;
    if (e < E) {
        int s = flag ? ei[2 * e] : ei[e];
        int d = flag ? ei[2 * ((long long)E + e)] : ei[E + e];
        int pos_ = atomicAdd(&g_cur[d], 1);
        g_csr_i[pos_] = s;
    }
}

// ---------------- layer 1: 2 threads/node gather + GEMM 3->64 (f32x2) ---------
// Thread pair (p=0,1) splits the edge range; combine via shfl_xor(1); each
// thread emits outputs [p*32, p*32+32) as 4 STG.128.
__global__ void __launch_bounds__(256)
layer1_kernel(const float* __restrict__ W1, const float* __restrict__ b1,
              __half* __restrict__ h1) {
    __shared__ __align__(16) float sW[3 * 64];
    __shared__ __align__(16) float sb[64];
    int t = threadIdx.x;
    for (int i = t; i < 3 * 64; i += 256) sW[i] = W1[i];
    if (t < 64) sb[t] = b1[t];
    __syncthreads();
    int idx = blockIdx.x * 256 + t;
    int v = idx >> 1;
    int p = idx & 1;
    bool ok = v < N_NODES;
    float a0 = 0.0f, a1 = 0.0f, a2 = 0.0f;
    float di = 0.0f;
    if (ok) {
        if (p == 0) g_indeg[v] = 0;   // self-clean for next call's prep
        di = g_dinv[v];
        int e0 = g_row_ptr[v], e1 = g_row_ptr[v + 1];
        int mid = e0 + ((e1 - e0 + 1) >> 1);
        int lo = p ? mid : e0;
        int hi = p ? e1 : mid;
        int e = lo;
        for (; e + 2 <= hi; e += 2) {
            float4 f0 = g_pos4[g_csr_i[e]];
            float4 f1 = g_pos4[g_csr_i[e + 1]];
            a0 += f0.x + f1.x;
            a1 += f0.y + f1.y;
            a2 += f0.z + f1.z;
        }
        if (e < hi) {
            float4 f = g_pos4[g_csr_i[e]];
            a0 += f.x; a1 += f.y; a2 += f.z;
        }
        if (p == 0) {   // self term added once
            float4 pv = g_pos4[v];
            a0 += pv.x; a1 += pv.y; a2 += pv.z;
        }
    }
    // pair combine (partner always same-validity)
    a0 += __shfl_xor_sync(0xFFFFFFFFu, a0, 1);
    a1 += __shfl_xor_sync(0xFFFFFFFFu, a1, 1);
    a2 += __shfl_xor_sync(0xFFFFFFFFu, a2, 1);
    if (!ok) return;
    a0 *= di; a1 *= di; a2 *= di;
    u64 xx0 = pack2(a0, a0), xx1 = pack2(a1, a1), xx2 = pack2(a2, a2);
    const u64* w0 = (const u64*)sW;
    const u64* w1 = (const u64*)(sW + 64);
    const u64* w2 = (const u64*)(sW + 128);
    const u64* bb = (const u64*)sb;
    __half2 tmp[16];
#pragma unroll
    for (int j = 0; j < 16; j++) {
        int j2 = p * 16 + j;
        u64 c = bb[j2];
        c = fma2(xx0, w0[j2], c);
        c = fma2(xx1, w1[j2], c);
        c = fma2(xx2, w2[j2], c);
        float lo, hi;
        unpack2(c, lo, hi);
        tmp[j] = __floats2half2_rn(di * fmaxf(lo, 0.0f), di * fmaxf(hi, 0.0f));
    }
    uint4* o = (uint4*)(h1 + (long long)v * 64 + p * 32);
    const uint4* src = (const uint4*)tmp;
#pragma unroll
    for (int j = 0; j < 4; j++) o[j] = src[j];
}

// ---------------- layer 2+3: gather(fp16) + GEMM64x64 + ReLU + GEMM64x24 ------
#define L2_NPB 64   // nodes per block: 8 warps x 2 nodes x 4 iterations
__global__ void __launch_bounds__(256)
layer2_kernel(const __half* __restrict__ h1, const float* __restrict__ W2,
              const float* __restrict__ b2, const float* __restrict__ W3,
              __half* __restrict__ y) {
    __shared__ __align__(16) float sW2[64 * 64];
    __shared__ __align__(16) float sW3[64 * 24];
    __shared__ __align__(16) float sb2[64];
    __shared__ __align__(16) float tile[16][64];
    int t = threadIdx.x;
    for (int i = t; i < 64 * 64; i += 256) sW2[i] = W2[i];
    for (int i = t; i < 64 * 24; i += 256) sW3[i] = W3[i];
    if (t < 64) sb2[t] = b2[t];
    __syncthreads();
    int warp = t >> 5, lane = t & 31;
    int half = lane >> 4, q = lane & 15;
    const u64* w2p = (const u64*)sW2;   // 32 u64 per k-row
    const u64* w3p = (const u64*)sW3;   // 12 u64 per k-row
#pragma unroll
    for (int it = 0; it < L2_NPB / 16; it++) {
        int vbase = blockIdx.x * L2_NPB + it * 16 + warp * 2;
        int v = vbase + half;
        // ---- gather (half-warp per node, 4 halves per lane, fp32 accum) ----
        float4 a = make_float4(0.0f, 0.0f, 0.0f, 0.0f);
        if (v < N_NODES) {
            float di = g_dinv[v];
            {
                uint2 u = ((const uint2*)(h1 + (long long)v * 64))[q];
                float2 fa = __half22float2(*(__half2*)&u.x);
                float2 fb = __half22float2(*(__half2*)&u.y);
                a = make_float4(fa.x, fa.y, fb.x, fb.y);
            }
            int e = g_row_ptr[v], end = g_row_ptr[v + 1];
            for (; e + 2 <= end; e += 2) {
                int s0 = g_csr_i[e], s1 = g_csr_i[e + 1];
                uint2 u0 = ((const uint2*)(h1 + (long long)s0 * 64))[q];
                uint2 u1 = ((const uint2*)(h1 + (long long)s1 * 64))[q];
                float2 fa0 = __half22float2(*(__half2*)&u0.x);
                float2 fb0 = __half22float2(*(__half2*)&u0.y);
                float2 fa1 = __half22float2(*(__half2*)&u1.x);
                float2 fb1 = __half22float2(*(__half2*)&u1.y);
                a.x += fa0.x + fa1.x;
                a.y += fa0.y + fa1.y;
                a.z += fb0.x + fb1.x;
                a.w += fb0.y + fb1.y;
            }
            if (e < end) {
                uint2 u = ((const uint2*)(h1 + (long long)g_csr_i[e] * 64))[q];
                float2 fa = __half22float2(*(__half2*)&u.x);
                float2 fb = __half22float2(*(__half2*)&u.y);
                a.x += fa.x; a.y += fa.y; a.z += fb.x; a.w += fb.y;
            }
            a.x *= di; a.y *= di; a.z *= di; a.w *= di;
        }
        ((float4*)tile[warp * 2 + half])[q] = a;
        __syncwarp();
        // ---- W2 GEMM + ReLU: warp handles its 2 nodes sequentially ----
#pragma unroll
        for (int s = 0; s < 2; s++) {
            int vv = vbase + s;
            if (vv >= N_NODES) continue;
            float dvv = g_dinv[vv];
            float* row = tile[warp * 2 + s];
            u64 c01 = ((const u64*)sb2)[lane];
#pragma unroll
            for (int k4 = 0; k4 < 16; k4++) {
                float4 xv = ((const float4*)row)[k4];
                float xs[4] = {xv.x, xv.y, xv.z, xv.w};
#pragma unroll
                for (int kk = 0; kk < 4; kk++) {
                    u64 xx = pack2(xs[kk], xs[kk]);
                    c01 = fma2(xx, w2p[(k4 * 4 + kk) * 32 + lane], c01);
                }
            }
            float c0, c1;
            unpack2(c01, c0, c1);
            c0 = dvv * fmaxf(c0, 0.0f);
            c1 = dvv * fmaxf(c1, 0.0f);
            __syncwarp();
            ((float2*)row)[lane] = make_float2(c0, c1);
            __syncwarp();
        }
        // ---- W3 GEMM: both nodes concurrently (lanes 0-11 / 16-27) ----
        {
            int vv = vbase + half;
            if (vv < N_NODES && q < 12) {
                float* row = tile[warp * 2 + half];
                u64 acc = 0ULL;
#pragma unroll
                for (int k4 = 0; k4 < 16; k4++) {
                    float4 xv = ((const float4*)row)[k4];
                    float xs[4] = {xv.x, xv.y, xv.z, xv.w};
#pragma unroll
                    for (int kk = 0; kk < 4; kk++) {
                        u64 xx = pack2(xs[kk], xs[kk]);
                        acc = fma2(xx, w3p[(k4 * 4 + kk) * 12 + q], acc);
                    }
                }
                float y0, y1;
                unpack2(acc, y0, y1);
                ((__half2*)(y + (long long)vv * 32))[q] = __floats2half2_rn(y0, y1);
            }
            __syncwarp();
        }
    }
}

// ---------------- layer 3 aggregate + pooling + fused final -------------------
__global__ void __launch_bounds__(256)
gather_pool_final_kernel(const __half* __restrict__ y, const float* __restrict__ b3,
                         float* __restrict__ out, int nblocks) {
    int t = threadIdx.x;
    int warp = t >> 5, lane = t & 31;
    int grp = lane >> 4, l = lane & 15;
    bool act = l < 12;
    int vbeg = (blockIdx.x * 8 + warp) * 8;
    if (vbeg < N_NODES) {
        float2 acc = make_float2(0.0f, 0.0f);
        int curg = -1;
#pragma unroll 1
        for (int u = 0; u < 8; u++) {
            int v = vbeg + u;
            if (v >= N_NODES) break;
            float2 a = make_float2(0.0f, 0.0f);
            int e0 = g_row_ptr[v], e1 = g_row_ptr[v + 1];
            for (int e = e0 + grp; e < e1; e += 2) {
                if (act) {
                    int s = g_csr_i[e];
                    float2 f = __half22float2(((const __half2*)(y + (long long)s * 32))[l]);
                    a.x += f.x; a.y += f.y;
                }
            }
            a.x += __shfl_xor_sync(0xFFFFFFFFu, a.x, 16);
            a.y += __shfl_xor_sync(0xFFFFFFFFu, a.y, 16);
            if (grp == 0 && act) {
                float2 sf = __half22float2(((const __half2*)(y + (long long)v * 32))[l]);
                a.x += sf.x; a.y += sf.y;
                float dv = g_dinv[v];
                a.x *= dv; a.y *= dv;
                int g = g_batch[v];
                if (g != curg) {
                    if (curg >= 0) {
                        atomicAdd(&g_sums[curg * 24 + 2 * l], acc.x);
                        atomicAdd(&g_sums[curg * 24 + 2 * l + 1], acc.y);
                    }
                    curg = g;
                    acc = a;
                } else {
                    acc.x += a.x;
                    acc.y += a.y;
                }
            }
        }
        if (grp == 0 && act && curg >= 0) {
            atomicAdd(&g_sums[curg * 24 + 2 * l], acc.x);
            atomicAdd(&g_sums[curg * 24 + 2 * l + 1], acc.y);
        }
    }
    __syncthreads();
    __shared__ int s_last;
    if (t == 0) {
        __threadfence();
        int old = atomicAdd(&g_done, 1);
        s_last = (old == nblocks - 1) ? 1 : 0;
    }
    __syncthreads();
    if (s_last) {
        __threadfence();
        for (int i = t; i < N_GRAPHS * 24; i += 256) {
            int g = i / 24, j = i % 24;
            float c = g_cnt[g];
            float m = (c > 0.0f) ? (g_sums[i] / c + b3[j]) : 0.0f;
            out[i] = tanhf(m);
        }
        __syncthreads();
        // reset persistent state for the next call
        for (int i = t; i < N_GRAPHS * 24; i += 256) g_sums[i] = 0.0f;
        if (t < N_GRAPHS) g_cnt[t] = 0.0f;
        for (int i = t; i < N_SCANB; i += 256) g_scan_flag[i] = 0ULL;
        if (t == 0) {
            g_done = 0;
            g_ready = 0;
            g_scan_done = 0;
        }
    }
}

// ---------------- launch -----------------------------------------------------
extern "C" void kernel_launch(void* const* d_in, const int* in_sizes, int n_in,
                              void* d_out, int out_size) {
    const float* pos   = (const float*)d_in[0];
    const int*   ei    = (const int*)d_in[1];   // int32 or int64 (detected)
    const int*   batch = (const int*)d_in[2];
    const float* W1    = (const float*)d_in[3];
    const float* b1    = (const float*)d_in[4];
    const float* W2    = (const float*)d_in[5];
    const float* b2    = (const float*)d_in[6];
    const float* W3    = (const float*)d_in[7];
    const float* b3    = (const float*)d_in[8];
    float*       out   = (float*)d_out;

    const int E = in_sizes[1] / 2;

    __half* h1; cudaGetSymbolAddress((void**)&h1, g_h16);
    __half* y;  cudaGetSymbolAddress((void**)&y, g_y16);

    const int TB = 256;
    auto grid = [&](long long n, int tb) { return (int)((n + tb - 1) / tb); };

    int pool_blocks = grid(N_NODES, 64);   // 8 warps/block x 8 nodes/warp

    prep_kernel<<<grid(E, TB), TB>>>(ei, batch, E);                           // #1
    scan_fill_kernel<<<grid(E, TB), TB>>>(pos, ei, E);                        // #2
    layer1_kernel<<<grid((long long)N_NODES * 2, 256), 256>>>(W1, b1, h1);    // #3
    layer2_kernel<<<grid(N_NODES, L2_NPB), 256>>>(h1, W2, b2, W3, y);         // #4 (profiled)
    gather_pool_final_kernel<<<pool_blocks, 256>>>(y, b3, out, pool_blocks);  // #5
}

// round 14
// speedup vs baseline: 1.2672x; 1.2672x over previous
#include <cuda_runtime.h>
#include <cuda_fp16.h>
#include <cstdint>

#define N_NODES 100000
#define N_GRAPHS 64
#define MAX_E    1600000
#define SCAN_B   1024
#define N_SCANB  ((N_NODES + SCAN_B - 1) / SCAN_B)   // 98

typedef unsigned long long u64;

// ---------------- f32x2 packed math (Blackwell) ------------------------------
__device__ __forceinline__ u64 pack2(float lo, float hi) {
    u64 r;
    asm("mov.b64 %0, {%1, %2};" : "=l"(r) : "f"(lo), "f"(hi));
    return r;
}
__device__ __forceinline__ void unpack2(u64 v, float& lo, float& hi) {
    asm("mov.b64 {%0, %1}, %2;" : "=f"(lo), "=f"(hi) : "l"(v));
}
__device__ __forceinline__ u64 fma2(u64 a, u64 b, u64 c) {
    u64 d;
    asm("fma.rn.f32x2 %0, %1, %2, %3;" : "=l"(d) : "l"(a), "l"(b), "l"(c));
    return d;
}

// ---------------- scratch (device globals; zero-initialized) ----------------
// Self-cleaning protocol: buffers needing zero/initial state at call start are
// reset by the END of the previous call (indeg by layer1; sums/cnt/scanflag/
// done by the fused final block). First call relies on static zero-init.
__device__ int   g_flag64;               // 1 if index buffers are int64
__device__ int   g_batch[N_NODES];
__device__ int   g_indeg[N_NODES];
__device__ float g_dinv[N_NODES];
__device__ int   g_row_ptr[N_NODES + 1];
__device__ int   g_cur[N_NODES];
__device__ u64   g_scan_flag[N_SCANB];   // hi32: status(1=agg,2=pref), lo32: value
__device__ int   g_done;                 // completion counter for fused final
__device__ __align__(16) int g_csr_i[MAX_E];            // src indices only
__device__ __align__(16) float4 g_pos4[N_NODES];        // dinv-scaled pos
__device__ __align__(16) __half g_h16[N_NODES * 64];    // scaled h1 activations
__device__ __align__(16) __half g_y16[N_NODES * 32];    // scaled pre-agg (stride 32)
__device__ float g_sums[N_GRAPHS * 24];
__device__ float g_cnt[N_GRAPHS];

// ---------------- prep: local dtype detect + batch + counts + degree ---------
__global__ void prep_kernel(const int* __restrict__ ei, const int* __restrict__ batch, int E) {
    __shared__ int s_nz[256];
    __shared__ float scnt[N_GRAPHS];
    int t = threadIdx.x;
    s_nz[t] = ei[2 * t + 1];   // E >= 256 always (1.6M)
    __syncthreads();
    for (int off = 128; off > 0; off >>= 1) {
        if (t < off) s_nz[t] |= s_nz[t + off];
        __syncthreads();
    }
    int flag = (s_nz[0] == 0) ? 1 : 0;
    if (blockIdx.x == 0 && t == 0) g_flag64 = flag;
    int i = blockIdx.x * blockDim.x + t;
    bool node_block = (blockIdx.x * blockDim.x) < N_NODES;
    if (node_block) {
        if (t < N_GRAPHS) scnt[t] = 0.0f;
        __syncthreads();
    }
    if (i < N_NODES) {
        int g = flag ? batch[2 * i] : batch[i];
        g_batch[i] = g;
        atomicAdd(&scnt[g], 1.0f);
    }
    if (i < E) {
        int d = flag ? ei[2 * ((long long)E + i)] : ei[E + i];
        atomicAdd(&g_indeg[d], 1);
    }
    if (node_block) {
        __syncthreads();
        if (t < N_GRAPHS && scnt[t] != 0.0f) atomicAdd(&g_cnt[t], scnt[t]);
    }
}

__device__ __forceinline__ int load_idx(const int* __restrict__ buf, long long i) {
    return g_flag64 ? buf[2 * i] : buf[(int)i];
}

// ---------------- single-pass scan + dinv + scaled pos4 ----------------------
__global__ void __launch_bounds__(SCAN_B)
scan_kernel(const float* __restrict__ pos, int E) {
    __shared__ int warp_x[32];
    __shared__ int s_prefix;
    int t = threadIdx.x, b = blockIdx.x;
    int lane = t & 31, wid = t >> 5;
    int i = b * SCAN_B + t;
    int v = (i < N_NODES) ? g_indeg[i] : 0;
    if (i < N_NODES) {
        float di = rsqrtf((float)(v + 1));   // +1 self-loop
        g_dinv[i] = di;
        g_pos4[i] = make_float4(di * pos[3 * i], di * pos[3 * i + 1],
                                di * pos[3 * i + 2], 0.0f);
    }
    int x = v;
#pragma unroll
    for (int off = 1; off < 32; off <<= 1) {
        int y = __shfl_up_sync(0xFFFFFFFFu, x, off);
        if (lane >= off) x += y;
    }
    if (lane == 31) warp_x[wid] = x;
    __syncthreads();
    if (wid == 0) {
        int w = warp_x[lane];
        int xs = w;
#pragma unroll
        for (int off = 1; off < 32; off <<= 1) {
            int y = __shfl_up_sync(0xFFFFFFFFu, xs, off);
            if (lane >= off) xs += y;
        }
        warp_x[lane] = xs - w;
        if (lane == 31) {
            u64 st = (b == 0) ? 2ULL : 1ULL;
            atomicExch(&g_scan_flag[b], (st << 32) | (unsigned int)xs);
        }
    }
    __syncthreads();
    int block_incl = x + warp_x[wid];
    if (wid == 0) {
        int prefix = 0;
        if (b > 0) {
            int j = b - 1;
            while (true) {
                int idx = j - lane;
                u64 pkt = (idx >= 0) ? atomicAdd(&g_scan_flag[idx], 0ULL) : (2ULL << 32);
                int st = (int)(pkt >> 32);
                unsigned rdy = __ballot_sync(0xFFFFFFFFu, st != 0);
                if (rdy != 0xFFFFFFFFu) continue;
                unsigned pm = __ballot_sync(0xFFFFFFFFu, st == 2);
                int stop = pm ? (__ffs(pm) - 1) : 32;
                int val = (lane <= stop) ? (int)(unsigned int)pkt : 0;
#pragma unroll
                for (int off = 16; off > 0; off >>= 1)
                    val += __shfl_down_sync(0xFFFFFFFFu, val, off);
                prefix += __shfl_sync(0xFFFFFFFFu, val, 0);
                if (stop < 32) break;
                j -= 32;
            }
        }
        if (lane == 0) s_prefix = prefix;
    }
    __syncthreads();
    int prefix = s_prefix;
    if (t == SCAN_B - 1)
        atomicExch(&g_scan_flag[b], (2ULL << 32) | (unsigned int)(prefix + block_incl));
    int excl = prefix + block_incl - v;
    if (i < N_NODES) {
        g_row_ptr[i] = excl;
        g_cur[i] = excl;
    }
    if (i == N_NODES) g_row_ptr[N_NODES] = E;
}

// ---------------- CSR fill (src only) -----------------------------------------
__global__ void fill_csr_kernel(const int* __restrict__ ei, int E) {
    int e = blockIdx.x * blockDim.x + threadIdx.x;
    if (e >= E) return;
    int s = load_idx(ei, e);
    int d = load_idx(ei, (long long)E + e);
    int pos = atomicAdd(&g_cur[d], 1);
    g_csr_i[pos] = s;
}

// ---------------- layer 1: thread-per-node gather + GEMM 3->64 (f32x2) --------
__global__ void __launch_bounds__(256)
layer1_kernel(const float* __restrict__ W1, const float* __restrict__ b1,
              __half* __restrict__ h1) {
    __shared__ __align__(16) float sW[3 * 64];
    __shared__ __align__(16) float sb[64];
    int t = threadIdx.x;
    for (int i = t; i < 3 * 64; i += 256) sW[i] = W1[i];
    if (t < 64) sb[t] = b1[t];
    __syncthreads();
    int v = blockIdx.x * 256 + t;
    if (v >= N_NODES) return;
    g_indeg[v] = 0;   // self-clean for next call's prep
    float4 pv = g_pos4[v];            // self (already dinv-scaled)
    float a0 = pv.x, a1 = pv.y, a2 = pv.z;
    int e = g_row_ptr[v], end = g_row_ptr[v + 1];
    for (; e < end && (e & 3); e++) {
        float4 f = g_pos4[g_csr_i[e]];
        a0 += f.x; a1 += f.y; a2 += f.z;
    }
    for (; e + 4 <= end; e += 4) {
        int4 s4 = *(const int4*)(g_csr_i + e);
        float4 f0 = g_pos4[s4.x];
        float4 f1 = g_pos4[s4.y];
        float4 f2 = g_pos4[s4.z];
        float4 f3 = g_pos4[s4.w];
        a0 += (f0.x + f1.x) + (f2.x + f3.x);
        a1 += (f0.y + f1.y) + (f2.y + f3.y);
        a2 += (f0.z + f1.z) + (f2.z + f3.z);
    }
    for (; e < end; e++) {
        float4 f = g_pos4[g_csr_i[e]];
        a0 += f.x; a1 += f.y; a2 += f.z;
    }
    float di = g_dinv[v];
    a0 *= di; a1 *= di; a2 *= di;
    u64 xx0 = pack2(a0, a0), xx1 = pack2(a1, a1), xx2 = pack2(a2, a2);
    const u64* w0 = (const u64*)sW;
    const u64* w1 = (const u64*)(sW + 64);
    const u64* w2 = (const u64*)(sW + 128);
    const u64* bb = (const u64*)sb;
    __half2 tmp[32];
#pragma unroll
    for (int j2 = 0; j2 < 32; j2++) {
        u64 c = bb[j2];
        c = fma2(xx0, w0[j2], c);
        c = fma2(xx1, w1[j2], c);
        c = fma2(xx2, w2[j2], c);
        float lo, hi;
        unpack2(c, lo, hi);
        tmp[j2] = __floats2half2_rn(di * fmaxf(lo, 0.0f), di * fmaxf(hi, 0.0f));
    }
    uint4* o = (uint4*)(h1 + (long long)v * 64);
    const uint4* src = (const uint4*)tmp;
#pragma unroll
    for (int j = 0; j < 8; j++) o[j] = src[j];
}

// ---------------- layer 2+3: gather(fp16) + node-blocked GEMMs (f32x2) --------
// Warp processes 4 nodes per GEMM pass: each weight LDS feeds 4 (W2) or 2 (W3)
// accumulators, cutting smem weight traffic 4x / 2x vs per-node streaming.
#define L2_NPB 64   // nodes per block: 8 warps x 4 nodes x 2 iterations
__global__ void __launch_bounds__(256)
layer2_kernel(const __half* __restrict__ h1, const float* __restrict__ W2,
              const float* __restrict__ b2, const float* __restrict__ W3,
              __half* __restrict__ y) {
    __shared__ __align__(16) float sW2[64 * 64];
    __shared__ __align__(16) float sW3[64 * 24];
    __shared__ __align__(16) float sb2[64];
    __shared__ __align__(16) float tile[32][64];   // 8 warps x 4 rows
    int t = threadIdx.x;
    for (int i = t; i < 64 * 64; i += 256) sW2[i] = W2[i];
    for (int i = t; i < 64 * 24; i += 256) sW3[i] = W3[i];
    if (t < 64) sb2[t] = b2[t];
    __syncthreads();
    int warp = t >> 5, lane = t & 31;
    int half = lane >> 4, q = lane & 15;
    const u64* w2p = (const u64*)sW2;   // 32 u64 per k-row
    const u64* w3p = (const u64*)sW3;   // 12 u64 per k-row
    float* trow = tile[warp * 4];       // this warp's 4 rows (contiguous)
#pragma unroll
    for (int it = 0; it < L2_NPB / 32; it++) {
        int vbase = blockIdx.x * L2_NPB + it * 32 + warp * 4;
        // ---- gather: 2 passes, half-warp per node, 4 halves per lane ----
#pragma unroll
        for (int pass = 0; pass < 2; pass++) {
            int v = vbase + pass * 2 + half;
            float4 a = make_float4(0.0f, 0.0f, 0.0f, 0.0f);
            if (v < N_NODES) {
                float di = g_dinv[v];
                {
                    uint2 u = ((const uint2*)(h1 + (long long)v * 64))[q];
                    float2 fa = __half22float2(*(__half2*)&u.x);
                    float2 fb = __half22float2(*(__half2*)&u.y);
                    a = make_float4(fa.x, fa.y, fb.x, fb.y);
                }
                int e = g_row_ptr[v], end = g_row_ptr[v + 1];
                for (; e + 2 <= end; e += 2) {
                    int s0 = g_csr_i[e], s1 = g_csr_i[e + 1];
                    uint2 u0 = ((const uint2*)(h1 + (long long)s0 * 64))[q];
                    uint2 u1 = ((const uint2*)(h1 + (long long)s1 * 64))[q];
                    float2 fa0 = __half22float2(*(__half2*)&u0.x);
                    float2 fb0 = __half22float2(*(__half2*)&u0.y);
                    float2 fa1 = __half22float2(*(__half2*)&u1.x);
                    float2 fb1 = __half22float2(*(__half2*)&u1.y);
                    a.x += fa0.x + fa1.x;
                    a.y += fa0.y + fa1.y;
                    a.z += fb0.x + fb1.x;
                    a.w += fb0.y + fb1.y;
                }
                if (e < end) {
                    uint2 u = ((const uint2*)(h1 + (long long)g_csr_i[e] * 64))[q];
                    float2 fa = __half22float2(*(__half2*)&u.x);
                    float2 fb = __half22float2(*(__half2*)&u.y);
                    a.x += fa.x; a.y += fa.y; a.z += fb.x; a.w += fb.y;
                }
                a.x *= di; a.y *= di; a.z *= di; a.w *= di;
            }
            ((float4*)(trow + (pass * 2 + half) * 64))[q] = a;
        }
        __syncwarp();
        // ---- W2 GEMM + ReLU: 4 nodes per weight load ----
        {
            u64 c[4];
#pragma unroll
            for (int m = 0; m < 4; m++) c[m] = ((const u64*)sb2)[lane];
#pragma unroll
            for (int k4 = 0; k4 < 16; k4++) {
                float4 x0 = *(const float4*)(trow + 0 * 64 + k4 * 4);
                float4 x1 = *(const float4*)(trow + 1 * 64 + k4 * 4);
                float4 x2 = *(const float4*)(trow + 2 * 64 + k4 * 4);
                float4 x3 = *(const float4*)(trow + 3 * 64 + k4 * 4);
                float xs0[4] = {x0.x, x0.y, x0.z, x0.w};
                float xs1[4] = {x1.x, x1.y, x1.z, x1.w};
                float xs2[4] = {x2.x, x2.y, x2.z, x2.w};
                float xs3[4] = {x3.x, x3.y, x3.z, x3.w};
#pragma unroll
                for (int kk = 0; kk < 4; kk++) {
                    u64 w = w2p[(k4 * 4 + kk) * 32 + lane];
                    c[0] = fma2(pack2(xs0[kk], xs0[kk]), w, c[0]);
                    c[1] = fma2(pack2(xs1[kk], xs1[kk]), w, c[1]);
                    c[2] = fma2(pack2(xs2[kk], xs2[kk]), w, c[2]);
                    c[3] = fma2(pack2(xs3[kk], xs3[kk]), w, c[3]);
                }
            }
            __syncwarp();
#pragma unroll
            for (int m = 0; m < 4; m++) {
                int vv = vbase + m;
                float dvv = (vv < N_NODES) ? g_dinv[vv] : 0.0f;
                float c0, c1;
                unpack2(c[m], c0, c1);
                c0 = dvv * fmaxf(c0, 0.0f);
                c1 = dvv * fmaxf(c1, 0.0f);
                ((float2*)(trow + m * 64))[lane] = make_float2(c0, c1);
            }
            __syncwarp();
        }
        // ---- W3 GEMM: group 0 (lanes 0-15) nodes 0,1; group 1 nodes 2,3 ----
        {
            u64 aA = 0ULL, aB = 0ULL;
            const float* rowA = trow + (half * 2 + 0) * 64;
            const float* rowB = trow + (half * 2 + 1) * 64;
            bool act = q < 12;
#pragma unroll
            for (int k4 = 0; k4 < 16; k4++) {
                float4 xA = *(const float4*)(rowA + k4 * 4);
                float4 xB = *(const float4*)(rowB + k4 * 4);
                float sA[4] = {xA.x, xA.y, xA.z, xA.w};
                float sB[4] = {xB.x, xB.y, xB.z, xB.w};
#pragma unroll
                for (int kk = 0; kk < 4; kk++) {
                    u64 w = act ? w3p[(k4 * 4 + kk) * 12 + q] : 0ULL;
                    aA = fma2(pack2(sA[kk], sA[kk]), w, aA);
                    aB = fma2(pack2(sB[kk], sB[kk]), w, aB);
                }
            }
            if (act) {
                int vA = vbase + half * 2;
                int vB = vA + 1;
                float y0, y1;
                if (vA < N_NODES) {
                    unpack2(aA, y0, y1);
                    ((__half2*)(g_y16 + (long long)vA * 32))[q] = __floats2half2_rn(y0, y1);
                }
                if (vB < N_NODES) {
                    unpack2(aB, y0, y1);
                    ((__half2*)(g_y16 + (long long)vB * 32))[q] = __floats2half2_rn(y0, y1);
                }
            }
            __syncwarp();
        }
    }
    (void)y;
}

// ---------------- layer 3 aggregate + pooling + fused final -------------------
__global__ void __launch_bounds__(256)
gather_pool_final_kernel(const __half* __restrict__ y, const float* __restrict__ b3,
                         float* __restrict__ out, int nblocks) {
    int t = threadIdx.x;
    int warp = t >> 5, lane = t & 31;
    int grp = lane >> 4, l = lane & 15;
    bool act = l < 12;
    int vbeg = (blockIdx.x * 8 + warp) * 8;
    if (vbeg < N_NODES) {
        float2 acc = make_float2(0.0f, 0.0f);
        int curg = -1;
#pragma unroll 1
        for (int u = 0; u < 8; u++) {
            int v = vbeg + u;
            if (v >= N_NODES) break;
            float2 a = make_float2(0.0f, 0.0f);
            int e0 = g_row_ptr[v], e1 = g_row_ptr[v + 1];
            for (int e = e0 + grp; e < e1; e += 2) {
                if (act) {
                    int s = g_csr_i[e];
                    float2 f = __half22float2(((const __half2*)(y + (long long)s * 32))[l]);
                    a.x += f.x; a.y += f.y;
                }
            }
            a.x += __shfl_xor_sync(0xFFFFFFFFu, a.x, 16);
            a.y += __shfl_xor_sync(0xFFFFFFFFu, a.y, 16);
            if (grp == 0 && act) {
                float2 sf = __half22float2(((const __half2*)(y + (long long)v * 32))[l]);
                a.x += sf.x; a.y += sf.y;
                float dv = g_dinv[v];
                a.x *= dv; a.y *= dv;
                int g = g_batch[v];
                if (g != curg) {
                    if (curg >= 0) {
                        atomicAdd(&g_sums[curg * 24 + 2 * l], acc.x);
                        atomicAdd(&g_sums[curg * 24 + 2 * l + 1], acc.y);
                    }
                    curg = g;
                    acc = a;
                } else {
                    acc.x += a.x;
                    acc.y += a.y;
                }
            }
        }
        if (grp == 0 && act && curg >= 0) {
            atomicAdd(&g_sums[curg * 24 + 2 * l], acc.x);
            atomicAdd(&g_sums[curg * 24 + 2 * l + 1], acc.y);
        }
    }
    __syncthreads();
    __shared__ int s_last;
    if (t == 0) {
        __threadfence();
        int old = atomicAdd(&g_done, 1);
        s_last = (old == nblocks - 1) ? 1 : 0;
    }
    __syncthreads();
    if (s_last) {
        __threadfence();
        for (int i = t; i < N_GRAPHS * 24; i += 256) {
            int g = i / 24, j = i % 24;
            float c = g_cnt[g];
            float m = (c > 0.0f) ? (g_sums[i] / c + b3[j]) : 0.0f;
            out[i] = tanhf(m);
        }
        __syncthreads();
        for (int i = t; i < N_GRAPHS * 24; i += 256) g_sums[i] = 0.0f;
        if (t < N_GRAPHS) g_cnt[t] = 0.0f;
        if (t < N_SCANB) g_scan_flag[t] = 0ULL;
        if (t == 0) g_done = 0;
    }
}

// ---------------- launch -----------------------------------------------------
extern "C" void kernel_launch(void* const* d_in, const int* in_sizes, int n_in,
                              void* d_out, int out_size) {
    const float* pos   = (const float*)d_in[0];
    const int*   ei    = (const int*)d_in[1];   // int32 or int64 (detected)
    const int*   batch = (const int*)d_in[2];
    const float* W1    = (const float*)d_in[3];
    const float* b1    = (const float*)d_in[4];
    const float* W2    = (const float*)d_in[5];
    const float* b2    = (const float*)d_in[6];
    const float* W3    = (const float*)d_in[7];
    const float* b3    = (const float*)d_in[8];
    float*       out   = (float*)d_out;

    const int E = in_sizes[1] / 2;

    __half* h1; cudaGetSymbolAddress((void**)&h1, g_h16);
    __half* y;  cudaGetSymbolAddress((void**)&y, g_y16);

    const int TB = 256;
    auto grid = [&](long long n, int tb) { return (int)((n + tb - 1) / tb); };

    int pool_blocks = grid(N_NODES, 64);   // 8 warps/block x 8 nodes/warp

    prep_kernel<<<grid(E, TB), TB>>>(ei, batch, E);                           // #1
    scan_kernel<<<N_SCANB, SCAN_B>>>(pos, E);                                 // #2
    fill_csr_kernel<<<grid(E, TB), TB>>>(ei, E);                              // #3
    layer1_kernel<<<grid(N_NODES, 256), 256>>>(W1, b1, h1);                   // #4 (profiled)
    layer2_kernel<<<grid(N_NODES, L2_NPB), 256>>>(h1, W2, b2, W3, y);         // #5
    gather_pool_final_kernel<<<pool_blocks, 256>>>(y, b3, out, pool_blocks);  // #6
}